// round 16
// baseline (speedup 1.0000x reference)
#include <cuda_runtime.h>
#include <cuda_fp16.h>
#include <math.h>
#include <stdint.h>

#define T_TOK 64
#define S_SP  729
#define H_DIM 1152
#define E_DIM 512
#define NE    9
#define NL    4
#define B_IMG 8
#define P_PAT 8

#define OUT_MAJOR 0
#define OUT_FINAL (T_TOK * 4 * H_DIM)
#define OUT_PREDS (OUT_FINAL + B_IMG * H_DIM)

__device__ float g_poolpart[B_IMG * 9 * H_DIM];
__device__ float g_hidden [B_IMG * E_DIM];
__device__ float g_cls    [B_IMG * E_DIM];
__device__ float g_puv    [NL * 17 * E_DIM];
__device__ float g_prompts[NL * B_IMG * NE * E_DIM];
__device__ float g_part   [(size_t)NL * T_TOK * 2 * 10 * S_SP];
__device__ float g_meanatt[T_TOK * NE * S_SP];
__device__ float g_pes    [T_TOK * NE];
__device__ float g_gsig   [T_TOK * 4];
__device__ float g_wq     [T_TOK * 4 * 736];
__device__ float g_sp     [T_TOK * 4];
__device__ float g_tokens [T_TOK * 4 * H_DIM];
__device__ float g_Q      [T_TOK * 4 * E_DIM];
__device__ float g_KQ     [T_TOK * 4 * H_DIM];
__device__ float g_qkb    [T_TOK * 4];
__device__ float g_law    [T_TOK * 4 * 736];
__device__ __align__(16) __half g_Whi[(size_t)NL * E_DIM * H_DIM];

#define WSCALE 32.0f

__device__ __forceinline__ uint32_t smem_u32(const void* p) {
    uint32_t a;
    asm("{ .reg .u64 t; cvta.to.shared.u64 t, %1; cvt.u32.u64 %0, t; }" : "=r"(a) : "l"(p));
    return a;
}
__device__ __forceinline__ void cpasync16(uint32_t dst, const void* src) {
    asm volatile("cp.async.cg.shared.global [%0], [%1], 16;" :: "r"(dst), "l"(src));
}
#define CP_COMMIT() asm volatile("cp.async.commit_group;" ::: "memory")
#define CP_WAIT1()  asm volatile("cp.async.wait_group 1;" ::: "memory")

__device__ __forceinline__ float blockSum256(float v) {
    __shared__ float red[8];
    int lane = threadIdx.x & 31, wid = threadIdx.x >> 5;
    #pragma unroll
    for (int o = 16; o; o >>= 1) v += __shfl_xor_sync(0xffffffffu, v, o);
    if (lane == 0) red[wid] = v;
    __syncthreads();
    if (wid == 0) {
        float r = (lane < 8) ? red[lane] : 0.f;
        #pragma unroll
        for (int o = 4; o; o >>= 1) r += __shfl_xor_sync(0xffffffffu, r, o);
        if (lane == 0) red[0] = r;
    }
    __syncthreads();
    float r = red[0];
    __syncthreads();
    return r;
}
__device__ __forceinline__ float blockMax256(float v) {
    __shared__ float red[8];
    int lane = threadIdx.x & 31, wid = threadIdx.x >> 5;
    #pragma unroll
    for (int o = 16; o; o >>= 1) v = fmaxf(v, __shfl_xor_sync(0xffffffffu, v, o));
    if (lane == 0) red[wid] = v;
    __syncthreads();
    if (wid == 0) {
        float r = (lane < 8) ? red[lane] : -INFINITY;
        #pragma unroll
        for (int o = 4; o; o >>= 1) r = fmaxf(r, __shfl_xor_sync(0xffffffffu, r, o));
        if (lane == 0) red[0] = r;
    }
    __syncthreads();
    float r = red[0];
    __syncthreads();
    return r;
}
__device__ __forceinline__ float gelu_exact(float x) {
    return 0.5f * x * (1.0f + erff(x * 0.7071067811865475f));
}
__device__ __forceinline__ uint32_t pk2h(__half a, __half b) {
    return ((uint32_t)__half_as_ushort(b) << 16) | (uint32_t)__half_as_ushort(a);
}
__device__ __forceinline__ void mmaf16(float* d, const uint32_t* a, uint32_t b0, uint32_t b1) {
    asm volatile(
        "mma.sync.aligned.m16n8k16.row.col.f32.f16.f16.f32 "
        "{%0,%1,%2,%3}, {%4,%5,%6,%7}, {%8,%9}, {%0,%1,%2,%3};"
        : "+f"(d[0]), "+f"(d[1]), "+f"(d[2]), "+f"(d[3])
        : "r"(a[0]), "r"(a[1]), "r"(a[2]), "r"(a[3]), "r"(b0), "r"(b1));
}

__global__ void k_wsplit(const float* __restrict__ sw) {
    const size_t N = (size_t)NL * E_DIM * H_DIM;
    for (size_t i = (size_t)blockIdx.x * 256 + threadIdx.x; i < N; i += (size_t)gridDim.x * 256)
        g_Whi[i] = __float2half(sw[i] * WSCALE);
}

__global__ void k_pool(const float* __restrict__ ov, const float* __restrict__ pw) {
    int b = blockIdx.x, sc = blockIdx.y, tid = threadIdx.x;
    float acc[9];
    #pragma unroll
    for (int j = 0; j < 9; j++) acc[j] = 0.f;
    const float* base = ov + (size_t)(b * P_PAT) * S_SP * H_DIM + (size_t)sc * 81 * H_DIM + tid;
    for (int s = 0; s < 81; s++) {
        float w = pw[sc * 81 + s];
        const float* p = base + (size_t)s * H_DIM;
        #pragma unroll
        for (int j = 0; j < 9; j++) acc[j] += w * p[j * 128];
    }
    #pragma unroll
    for (int j = 0; j < 9; j++)
        g_poolpart[((size_t)b * 9 + sc) * H_DIM + tid + j * 128] = acc[j];
}

__global__ void k_cls1(const float* __restrict__ w1, const float* __restrict__ b1,
                       const float* __restrict__ pb) {
    __shared__ float pr[B_IMG * H_DIM];
    int tid = threadIdx.x, wid = tid >> 5, lane = tid & 31;
    float pbias = pb[0];
    for (int idx = tid; idx < B_IMG * H_DIM; idx += 256) {
        int b = idx / H_DIM, h = idx - b * H_DIM;
        float s = pbias;
        #pragma unroll
        for (int sc = 0; sc < 9; sc++) s += g_poolpart[((size_t)b * 9 + sc) * H_DIM + h];
        pr[idx] = s;
    }
    __syncthreads();
    int o = blockIdx.x * 8 + wid;
    float acc[8];
    #pragma unroll
    for (int b = 0; b < 8; b++) acc[b] = 0.f;
    const float* wr = w1 + (size_t)o * H_DIM;
    for (int k = lane; k < H_DIM; k += 32) {
        float w = wr[k];
        #pragma unroll
        for (int b = 0; b < 8; b++) acc[b] += w * pr[b * H_DIM + k];
    }
    #pragma unroll
    for (int b = 0; b < 8; b++)
        #pragma unroll
        for (int off = 16; off; off >>= 1) acc[b] += __shfl_xor_sync(0xffffffffu, acc[b], off);
    if (lane == 0) {
        float bv = b1[o];
        #pragma unroll
        for (int b = 0; b < 8; b++) g_hidden[b * E_DIM + o] = gelu_exact(acc[b] + bv);
    }
}

__global__ void k_cls2(const float* __restrict__ w2, const float* __restrict__ b2) {
    __shared__ float hr[B_IMG * E_DIM];
    int tid = threadIdx.x, wid = tid >> 5, lane = tid & 31;
    for (int idx = tid; idx < B_IMG * E_DIM; idx += 256) hr[idx] = g_hidden[idx];
    __syncthreads();
    int o = blockIdx.x * 8 + wid;
    float acc[8];
    #pragma unroll
    for (int b = 0; b < 8; b++) acc[b] = 0.f;
    const float* wr = w2 + (size_t)o * E_DIM;
    for (int k = lane; k < E_DIM; k += 32) {
        float w = wr[k];
        #pragma unroll
        for (int b = 0; b < 8; b++) acc[b] += w * hr[b * E_DIM + k];
    }
    #pragma unroll
    for (int b = 0; b < 8; b++)
        #pragma unroll
        for (int off = 16; off; off >>= 1) acc[b] += __shfl_xor_sync(0xffffffffu, acc[b], off);
    if (lane == 0) {
        float bv = b2[o];
        #pragma unroll
        for (int b = 0; b < 8; b++) g_cls[b * E_DIM + o] = acc[b] + bv;
    }
}

__global__ void k_puv(const float* __restrict__ emo, const float* __restrict__ pw) {
    int oc = blockIdx.x, i = blockIdx.y;
    int tid = threadIdx.x, wid = tid >> 5, lane = tid & 31;
    __shared__ float es[NE * E_DIM];
    __shared__ float cs[B_IMG * E_DIM];
    for (int idx = tid; idx < NE * E_DIM; idx += 256) es[idx] = emo[idx];
    for (int idx = tid; idx < B_IMG * E_DIM; idx += 256) cs[idx] = g_cls[idx];
    __syncthreads();
    for (int oi = wid; oi < 32; oi += 8) {
        int o = oc * 32 + oi;
        const float* wr = pw + ((size_t)i * E_DIM + o) * 1024;
        float acc[17];
        #pragma unroll
        for (int j = 0; j < 17; j++) acc[j] = 0.f;
        for (int c = lane; c < 512; c += 32) {
            float w1 = wr[c];
            #pragma unroll
            for (int n = 0; n < NE; n++) acc[n] += w1 * es[n * 512 + c];
            float w2 = wr[512 + c];
            #pragma unroll
            for (int b = 0; b < B_IMG; b++) acc[9 + b] += w2 * cs[b * 512 + c];
        }
        #pragma unroll
        for (int j = 0; j < 17; j++)
            #pragma unroll
            for (int off = 16; off; off >>= 1) acc[j] += __shfl_xor_sync(0xffffffffu, acc[j], off);
        if (lane == 0) {
            #pragma unroll
            for (int j = 0; j < 17; j++) g_puv[((size_t)i * 17 + j) * 512 + o] = acc[j];
        }
    }
}

__global__ void k_prompts2(const float* __restrict__ pb) {
    int n = blockIdx.x, b = blockIdx.y, i = blockIdx.z;
    int tid = threadIdx.x;
    int o1 = tid, o2 = tid + 256;
    float r1 = g_puv[((size_t)i * 17 + n) * 512 + o1] + g_puv[((size_t)i * 17 + 9 + b) * 512 + o1]
             + pb[i * 512 + o1];
    float r2 = g_puv[((size_t)i * 17 + n) * 512 + o2] + g_puv[((size_t)i * 17 + 9 + b) * 512 + o2]
             + pb[i * 512 + o2];
    float nrm = blockSum256(r1 * r1 + r2 * r2);
    float inv = rsqrtf(nrm);
    size_t base = ((size_t)(i * B_IMG + b) * NE + n) * E_DIM;
    g_prompts[base + o1] = r1 * inv;
    g_prompts[base + o2] = r2 * inv;
}

// ======= sig GEMM: fp16 single product, KSTEP=64, grid (12,64,8), 2 CTA/SM =======
#define NCH 18
#define SM2_PSM   0          // 9216
#define SM2_SBI   9216       // 1024
#define SM2_RED   10240      // 2560
#define SM2_A     12800      // 2 bufs x (64 rows x 144B) = 18432 -> ends 31232
#define SM2_W     31232      // 2 bufs x (256 rows x 144B) = 73728 -> ends 104960
#define SM2_YSM   12800      // union: 64*260*4 = 66560 -> ends 79360
#define SM2_TOTAL 104960
#define Y_STR 260
#define A_RS 144
#define A_WS 36

__global__ void __launch_bounds__(256, 2)
k_sig_mma(const float* __restrict__ sig, const float* __restrict__ sb) {
    extern __shared__ char smem[];
    uint32_t sbase = smem_u32(smem);
    float* Psm = reinterpret_cast<float*>(smem + SM2_PSM);
    float* Sbi = reinterpret_cast<float*>(smem + SM2_SBI);
    float* red = reinterpret_cast<float*>(smem + SM2_RED);
    float* ysm = reinterpret_cast<float*>(smem + SM2_YSM);

    int tid = threadIdx.x, wid = tid >> 5, lane = tid & 31;
    int wm = wid >> 2, wn = wid & 3;
    int g = lane >> 2, tig = lane & 3;
    int s0 = blockIdx.x * 64;
    int t = blockIdx.y;
    int i = blockIdx.z >> 1, half = blockIdx.z & 1;
    int b = t >> 3;

    {
        size_t pbase = ((size_t)(i * B_IMG + b) * NE) * E_DIM + half * 256;
        for (int idx = tid; idx < NE * 256; idx += 256) {
            int n = idx >> 8, cc = idx & 255;
            Psm[idx] = g_prompts[pbase + (size_t)n * E_DIM + cc];
        }
        for (int idx = tid; idx < 256; idx += 256)
            Sbi[idx] = WSCALE * sb[i * E_DIM + half * 256 + idx];
        for (int idx = tid; idx < 640; idx += 256) red[idx] = 0.f;
    }

    const float* Xbase = sig + ((size_t)(i * T_TOK + t) * S_SP) * H_DIM;
    const char* WH = reinterpret_cast<const char*>(g_Whi)
                   + ((size_t)i * E_DIM + half * 256) * H_DIM * 2;

    float acc[2][8][4];
    #pragma unroll
    for (int mt = 0; mt < 2; mt++)
        #pragma unroll
        for (int nt = 0; nt < 8; nt++)
            #pragma unroll
            for (int c = 0; c < 4; c++) acc[mt][nt][c] = 0.f;

    int xrow = tid >> 2, xkc = tid & 3;       // 64 rows, 4 threads/row, 16 floats each
    int xs = s0 + xrow;
    const float* xptr = (xs < S_SP) ? (Xbase + (size_t)xs * H_DIM + xkc * 16) : nullptr;
    float xv[16];

#define ISSUE_W(CH, BUF) do { \
    const char* sH = WH + ((size_t)tid * H_DIM + (CH) * 64) * 2; \
    uint32_t dH = sbase + SM2_W + (BUF) * 36864 + tid * A_RS; \
    cpasync16(dH, sH); cpasync16(dH + 16, sH + 16); \
    cpasync16(dH + 32, sH + 32); cpasync16(dH + 48, sH + 48); \
    cpasync16(dH + 64, sH + 64); cpasync16(dH + 80, sH + 80); \
    cpasync16(dH + 96, sH + 96); cpasync16(dH + 112, sH + 112); \
} while (0)

#define LOAD_X(CH) do { \
    if (xptr) { \
        const float* p_ = xptr + (CH) * 64; \
        _Pragma("unroll") \
        for (int q_ = 0; q_ < 4; q_++) { \
            float4 f_ = *reinterpret_cast<const float4*>(p_ + q_ * 4); \
            xv[q_*4+0]=f_.x; xv[q_*4+1]=f_.y; xv[q_*4+2]=f_.z; xv[q_*4+3]=f_.w; \
        } \
    } else { \
        _Pragma("unroll") for (int j_ = 0; j_ < 16; j_++) xv[j_] = 0.f; \
    } \
} while (0)

#define STORE_A(BUF) do { \
    uint32_t hq_[8]; \
    _Pragma("unroll") \
    for (int j_ = 0; j_ < 8; j_++) \
        hq_[j_] = pk2h(__float2half(xv[2*j_]), __float2half(xv[2*j_+1])); \
    char* aH = smem + SM2_A + (BUF) * 9216 + xrow * A_RS + xkc * 32; \
    *reinterpret_cast<uint4*>(aH)      = make_uint4(hq_[0], hq_[1], hq_[2], hq_[3]); \
    *reinterpret_cast<uint4*>(aH + 16) = make_uint4(hq_[4], hq_[5], hq_[6], hq_[7]); \
} while (0)

    ISSUE_W(0, 0); CP_COMMIT();
    LOAD_X(0);
    ISSUE_W(1, 1); CP_COMMIT();
    STORE_A(0);
    LOAD_X(1);

    for (int ch = 0; ch < NCH; ch++) {
        int buf = ch & 1;
        if (ch > 0) {
            STORE_A(buf);
            if (ch + 1 < NCH) LOAD_X(ch + 1);
        }
        CP_WAIT1();
        __syncthreads();

        const uint32_t* AH  = reinterpret_cast<const uint32_t*>(smem + SM2_A + buf * 9216);
        const uint32_t* WHs = reinterpret_cast<const uint32_t*>(smem + SM2_W + buf * 36864);

        #pragma unroll
        for (int h = 0; h < 4; h++) {
            uint32_t ah[2][4];
            #pragma unroll
            for (int mt = 0; mt < 2; mt++) {
                int base = (wm * 32 + mt * 16 + g) * A_WS + h * 8 + tig;
                ah[mt][0] = AH[base];     ah[mt][1] = AH[base + 8 * A_WS];
                ah[mt][2] = AH[base + 4]; ah[mt][3] = AH[base + 8 * A_WS + 4];
            }
            #pragma unroll
            for (int nt = 0; nt < 8; nt++) {
                int wb = (wn * 64 + nt * 8 + g) * A_WS + h * 8 + tig;
                uint32_t b0h = WHs[wb], b1h = WHs[wb + 4];
                mmaf16(acc[0][nt], ah[0], b0h, b1h);
                mmaf16(acc[1][nt], ah[1], b0h, b1h);
            }
        }
        __syncthreads();
        if (ch + 2 < NCH) ISSUE_W(ch + 2, buf);
        CP_COMMIT();
    }

    // epilogue (scale-invariant): bias(x32) + partial L2-norm + partial prompt dots
    #pragma unroll
    for (int mt = 0; mt < 2; mt++) {
        int row = wm * 32 + mt * 16 + g;
        #pragma unroll
        for (int nt = 0; nt < 8; nt++) {
            int col = wn * 64 + nt * 8 + tig * 2;
            float b0 = Sbi[col], b1 = Sbi[col + 1];
            *reinterpret_cast<float2*>(&ysm[row * Y_STR + col]) =
                make_float2(acc[mt][nt][0] + b0, acc[mt][nt][1] + b1);
            *reinterpret_cast<float2*>(&ysm[(row + 8) * Y_STR + col]) =
                make_float2(acc[mt][nt][2] + b0, acc[mt][nt][3] + b1);
        }
    }
    __syncthreads();
    for (int r8 = 0; r8 < 8; r8++) {
        int row = wid * 8 + r8;
        float v[10];
        #pragma unroll
        for (int j = 0; j < 10; j++) v[j] = 0.f;
        for (int cc = lane; cc < 256; cc += 32) {
            float y = ysm[row * Y_STR + cc];
            v[0] += y * y;
            #pragma unroll
            for (int n = 0; n < NE; n++) v[1 + n] += y * Psm[n * 256 + cc];
        }
        #pragma unroll
        for (int j = 0; j < 10; j++)
            #pragma unroll
            for (int off = 16; off; off >>= 1) v[j] += __shfl_xor_sync(0xffffffffu, v[j], off);
        if (lane == 0) {
            #pragma unroll
            for (int j = 0; j < 10; j++) red[row * 10 + j] = v[j];
        }
    }
    __syncthreads();

    if (tid < 64) {
        int s = s0 + tid;
        if (s < S_SP) {
            size_t base = ((((size_t)i * T_TOK + t) * 2 + half) * 10) * S_SP + s;
            #pragma unroll
            for (int j = 0; j < 10; j++)
                g_part[base + (size_t)j * S_SP] = red[tid * 10 + j];
        }
    }
#undef ISSUE_W
#undef LOAD_X
#undef STORE_A
}

__global__ void k_softmax_mean() {
    int tn = blockIdx.x;
    int t = tn / NE, n = tn % NE;
    int tid = threadIdx.x;
    float accm[3] = {0.f, 0.f, 0.f};
    for (int i = 0; i < NL; i++) {
        const float* p0 = g_part + ((((size_t)i * T_TOK + t) * 2 + 0) * 10) * S_SP;
        const float* p1 = g_part + ((((size_t)i * T_TOK + t) * 2 + 1) * 10) * S_SP;
        float x[3];
        float mx = -INFINITY;
        #pragma unroll
        for (int j = 0; j < 3; j++) {
            int s = tid + j * 256;
            if (s < S_SP) {
                float nsq = p0[s] + p1[s];
                float d = p0[(size_t)(1 + n) * S_SP + s] + p1[(size_t)(1 + n) * S_SP + s];
                x[j] = 100.f * d * rsqrtf(nsq);
            } else x[j] = -INFINITY;
            mx = fmaxf(mx, x[j]);
        }
        mx = blockMax256(mx);
        float lsum = 0.f;
        float e[3];
        #pragma unroll
        for (int j = 0; j < 3; j++) {
            int s = tid + j * 256;
            e[j] = (s < S_SP) ? expf(x[j] - mx) : 0.f;
            lsum += e[j];
        }
        float tot = blockSum256(lsum);
        float inv = 0.25f / tot;
        #pragma unroll
        for (int j = 0; j < 3; j++) accm[j] += e[j] * inv;
    }
    float psum = 0.f;
    size_t obase = ((size_t)t * NE + n) * S_SP;
    #pragma unroll
    for (int j = 0; j < 3; j++) {
        int s = tid + j * 256;
        if (s < S_SP) {
            g_meanatt[obase + s] = accm[j];
            psum += accm[j];
        }
    }
    float tot = blockSum256(psum);
    if (tid == 0) g_pes[t * NE + n] = tot / (float)S_SP;
}

__global__ void k_matt() {
    int t = blockIdx.x, tid = threadIdx.x;
    float bsum[4] = {0.f, 0.f, 0.f, 0.f};
    #pragma unroll
    for (int j = 0; j < 3; j++) {
        int s = tid + j * 256;
        if (s < S_SP) {
            float m = -INFINITY;
            #pragma unroll
            for (int n = 0; n < NE; n++)
                m = fmaxf(m, g_meanatt[((size_t)t * NE + n) * S_SP + s]);
            int r = s / 27, c = s - r * 27;
            float w0 = (r < 14 && c < 14) ? m : 0.f;
            float w1 = (r < 14 && c >= 13) ? m : 0.f;
            float w2 = (r >= 13 && c < 14) ? m : 0.f;
            float w3 = (r >= 13 && c >= 13) ? m : 0.f;
            size_t wb = (size_t)t * 4 * 736 + s;
            g_wq[wb] = w0;
            g_wq[wb + 736] = w1;
            g_wq[wb + 1472] = w2;
            g_wq[wb + 2208] = w3;
            bsum[0] += w0; bsum[1] += w1; bsum[2] += w2; bsum[3] += w3;
        }
    }
    #pragma unroll
    for (int q = 0; q < 4; q++) {
        float tot = blockSum256(bsum[q]);
        if (tid == 0) g_sp[t * 4 + q] = tot / 196.f;
    }
    if (tid == 0) {
        float pm = -INFINITY;
        for (int n = 0; n < NE; n++) pm = fmaxf(pm, g_pes[t * NE + n]);
        g_gsig[t * 4 + 0] = g_sp[t * 4 + 0] * pm;
        g_gsig[t * 4 + 1] = g_sp[t * 4 + 1] * pm;
        g_gsig[t * 4 + 2] = g_sp[t * 4 + 2] * pm;
        g_gsig[t * 4 + 3] = g_sp[t * 4 + 3] * pm;
    }
}

__global__ void k_tok(const float* __restrict__ ov) {
    __shared__ float wqs[4 * 736];
    __shared__ float sps[4];
    int t = blockIdx.x, hc = blockIdx.y, tid = threadIdx.x;
    for (int idx = tid; idx < 4 * 736; idx += 128) wqs[idx] = g_wq[(size_t)t * 4 * 736 + idx];
    if (tid < 4) sps[tid] = g_sp[t * 4 + tid];
    __syncthreads();
    int h = hc * 128 + tid;
    float a0 = 0.f, a1 = 0.f, a2 = 0.f, a3 = 0.f;
    const float* base = ov + ((size_t)t * S_SP) * H_DIM + h;
    for (int s = 0; s < S_SP; s++) {
        float v = base[(size_t)s * H_DIM];
        a0 += v * wqs[s];
        a1 += v * wqs[736 + s];
        a2 += v * wqs[1472 + s];
        a3 += v * wqs[2208 + s];
    }
    g_tokens[((size_t)t * 4 + 0) * H_DIM + h] = (a0 * (1.f / 196.f)) / (sps[0] + 1e-8f);
    g_tokens[((size_t)t * 4 + 1) * H_DIM + h] = (a1 * (1.f / 196.f)) / (sps[1] + 1e-8f);
    g_tokens[((size_t)t * 4 + 2) * H_DIM + h] = (a2 * (1.f / 196.f)) / (sps[2] + 1e-8f);
    g_tokens[((size_t)t * 4 + 3) * H_DIM + h] = (a3 * (1.f / 196.f)) / (sps[3] + 1e-8f);
}

__global__ void k_qproj(const float* __restrict__ qw, const float* __restrict__ qb) {
    int t = blockIdx.x, tid = threadIdx.x;
    __shared__ float toks[4 * H_DIM];
    for (int idx = tid; idx < 4 * H_DIM; idx += 256) toks[idx] = g_tokens[(size_t)t * 4 * H_DIM + idx];
    __syncthreads();
    int wid = tid >> 5, lane = tid & 31;
    for (int o = wid; o < E_DIM; o += 8) {
        float acc[4] = {0.f, 0.f, 0.f, 0.f};
        const float* wr = qw + (size_t)o * H_DIM;
        for (int k = lane; k < H_DIM; k += 32) {
            float w = wr[k];
            #pragma unroll
            for (int q = 0; q < 4; q++) acc[q] += w * toks[q * H_DIM + k];
        }
        #pragma unroll
        for (int off = 16; off; off >>= 1)
            #pragma unroll
            for (int q = 0; q < 4; q++) acc[q] += __shfl_xor_sync(0xffffffffu, acc[q], off);
        if (lane == 0) {
            float bv = qb[o];
            #pragma unroll
            for (int q = 0; q < 4; q++) g_Q[((size_t)t * 4 + q) * E_DIM + o] = acc[q] + bv;
        }
    }
}

__global__ void k_kq(const float* __restrict__ kw, const float* __restrict__ kb) {
    int t = blockIdx.x, hc = blockIdx.y;
    int tid = threadIdx.x;
    __shared__ float Qs[4 * E_DIM];
    for (int idx = tid; idx < 4 * E_DIM; idx += 256) Qs[idx] = g_Q[(size_t)t * 4 * E_DIM + idx];
    __syncthreads();
    int h = hc * 128 + (tid >> 1);
    int q0 = (tid & 1) * 2;
    float a0 = 0.f, a1 = 0.f;
    const float* kcol = kw + h;
    for (int e = 0; e < E_DIM; e++) {
        float kv = kcol[(size_t)e * H_DIM];
        a0 += kv * Qs[(q0 + 0) * E_DIM + e];
        a1 += kv * Qs[(q0 + 1) * E_DIM + e];
    }
    g_KQ[((size_t)t * 4 + q0 + 0) * H_DIM + h] = a0;
    g_KQ[((size_t)t * 4 + q0 + 1) * H_DIM + h] = a1;

    if (hc == 0 && tid < 128) {
        int wid = tid >> 5, lane = tid & 31;
        float acc = 0.f;
        for (int e = lane; e < E_DIM; e += 32) acc += Qs[wid * E_DIM + e] * kb[e];
        #pragma unroll
        for (int off = 16; off; off >>= 1) acc += __shfl_xor_sync(0xffffffffu, acc, off);
        if (lane == 0) g_qkb[t * 4 + wid] = acc;
    }
}

__global__ void k_logits(const float* __restrict__ ov) {
    __shared__ float KQs[4 * H_DIM];
    __shared__ float qkbs[4];
    int t = blockIdx.x, sc = blockIdx.y, tid = threadIdx.x;
    int wid = tid >> 5, lane = tid & 31;
    for (int idx = tid; idx < 4 * H_DIM; idx += 128) KQs[idx] = g_KQ[(size_t)t * 4 * H_DIM + idx];
    if (tid < 4) qkbs[tid] = g_qkb[t * 4 + tid];
    __syncthreads();
    const float RS = 0.04419417382415922f;
    for (int s = sc * 128 + wid; s < min(sc * 128 + 128, S_SP); s += 4) {
        float acc[4] = {0.f, 0.f, 0.f, 0.f};
        const float* orow = ov + ((size_t)t * S_SP + s) * H_DIM;
        for (int h = lane; h < H_DIM; h += 32) {
            float vv = orow[h];
            #pragma unroll
            for (int q = 0; q < 4; q++) acc[q] += vv * KQs[q * H_DIM + h];
        }
        #pragma unroll
        for (int off = 16; off; off >>= 1)
            #pragma unroll
            for (int q = 0; q < 4; q++) acc[q] += __shfl_xor_sync(0xffffffffu, acc[q], off);
        if (lane == 0) {
            #pragma unroll
            for (int q = 0; q < 4; q++)
                g_law[((size_t)t * 4 + q) * 736 + s] = (acc[q] + qkbs[q]) * RS;
        }
    }
}

__global__ void k_soft4() {
    int t = blockIdx.x, tid = threadIdx.x;
    for (int q = 0; q < 4; q++) {
        float* L = g_law + ((size_t)t * 4 + q) * 736;
        float x[3];
        float mx = -INFINITY;
        #pragma unroll
        for (int j = 0; j < 3; j++) {
            int s = tid + j * 256;
            x[j] = (s < S_SP) ? L[s] : -INFINITY;
            mx = fmaxf(mx, x[j]);
        }
        mx = blockMax256(mx);
        float lsum = 0.f;
        float e[3];
        #pragma unroll
        for (int j = 0; j < 3; j++) {
            int s = tid + j * 256;
            e[j] = (s < S_SP) ? expf(x[j] - mx) : 0.f;
            lsum += e[j];
        }
        float tot = blockSum256(lsum);
        float inv = 1.f / tot;
        #pragma unroll
        for (int j = 0; j < 3; j++) {
            int s = tid + j * 256;
            if (s < S_SP) L[s] = e[j] * inv;
        }
    }
}

__global__ void k_major(const float* __restrict__ ov, float* __restrict__ out) {
    __shared__ float law[4 * 736];
    int t = blockIdx.x, hc = blockIdx.y, tid = threadIdx.x;
    for (int idx = tid; idx < 4 * 736; idx += 128) {
        int q = idx / 736, s = idx - q * 736;
        law[idx] = (s < S_SP) ? g_law[((size_t)t * 4 + q) * 736 + s] : 0.f;
    }
    __syncthreads();
    int h = hc * 128 + tid;
    float a0 = 0.f, a1 = 0.f, a2 = 0.f, a3 = 0.f;
    const float* base = ov + ((size_t)t * S_SP) * H_DIM + h;
    for (int s = 0; s < S_SP; s++) {
        float v = base[(size_t)s * H_DIM];
        a0 += v * law[s];
        a1 += v * law[736 + s];
        a2 += v * law[1472 + s];
        a3 += v * law[2208 + s];
    }
    out[OUT_MAJOR + ((size_t)t * 4 + 0) * H_DIM + h] = a0;
    out[OUT_MAJOR + ((size_t)t * 4 + 1) * H_DIM + h] = a1;
    out[OUT_MAJOR + ((size_t)t * 4 + 2) * H_DIM + h] = a2;
    out[OUT_MAJOR + ((size_t)t * 4 + 3) * H_DIM + h] = a3;
}

__global__ void k_finpred(const float* __restrict__ w1, const float* __restrict__ b1,
                          const float* __restrict__ w2, const float* __restrict__ b2,
                          float* __restrict__ out) {
    int b = blockIdx.x, tid = threadIdx.x;
    __shared__ float gsh[32];
    __shared__ float gsum_sh;
    __shared__ float fr[H_DIM];
    __shared__ float hid[E_DIM];
    __shared__ float lg[NE];
    if (tid < 32) {
        int p = tid >> 2, q = tid & 3;
        gsh[tid] = g_gsig[(b * P_PAT + p) * 4 + q];
    }
    __syncthreads();
    if (tid == 0) {
        float s = 0.f;
        for (int i = 0; i < 32; i++) s += gsh[i];
        gsum_sh = s;
    }
    __syncthreads();
    float denom = gsum_sh / 32.f + 1e-8f;
    int nh = (tid < 128) ? 5 : 4;
    for (int j = 0; j < nh; j++) {
        int h = tid + j * 256;
        float acc = 0.f;
        for (int idx = 0; idx < 32; idx++) {
            int p = idx >> 2, q = idx & 3;
            acc += out[OUT_MAJOR + ((size_t)(b * P_PAT + p) * 4 + q) * H_DIM + h] * gsh[idx];
        }
        float fin = (acc / 32.f) / denom;
        fr[h] = fin;
        out[OUT_FINAL + (size_t)b * H_DIM + h] = fin;
    }
    __syncthreads();
    int wid = tid >> 5, lane = tid & 31;
    for (int o = wid; o < E_DIM; o += 8) {
        float acc = 0.f;
        const float* wr = w1 + (size_t)o * H_DIM;
        for (int k = lane; k < H_DIM; k += 32) acc += wr[k] * fr[k];
        #pragma unroll
        for (int off = 16; off; off >>= 1) acc += __shfl_xor_sync(0xffffffffu, acc, off);
        if (lane == 0) hid[o] = gelu_exact(acc + b1[o]);
    }
    __syncthreads();
    for (int n = 0; n < NE; n++) {
        float v = hid[tid] * w2[n * E_DIM + tid] + hid[tid + 256] * w2[n * E_DIM + tid + 256];
        float tot = blockSum256(v);
        if (tid == 0) lg[n] = tot + b2[n];
    }
    __syncthreads();
    if (tid == 0) {
        float mx = -INFINITY;
        for (int n = 0; n < NE; n++) mx = fmaxf(mx, lg[n]);
        float sum = 0.f;
        float e[NE];
        for (int n = 0; n < NE; n++) { e[n] = expf(lg[n] - mx); sum += e[n]; }
        for (int n = 0; n < NE; n++) out[OUT_PREDS + b * NE + n] = e[n] / sum;
    }
}

extern "C" void kernel_launch(void* const* d_in, const int* in_sizes, int n_in,
                              void* d_out, int out_size) {
    const float* ov      = (const float*)d_in[0];
    const float* sig     = (const float*)d_in[1];
    const float* emo     = (const float*)d_in[2];
    const float* pool_w  = (const float*)d_in[3];
    const float* pool_b  = (const float*)d_in[4];
    const float* cls_w1  = (const float*)d_in[5];
    const float* cls_b1  = (const float*)d_in[6];
    const float* cls_w2  = (const float*)d_in[7];
    const float* cls_b2  = (const float*)d_in[8];
    const float* sig_w   = (const float*)d_in[9];
    const float* sig_b   = (const float*)d_in[10];
    const float* prm_w   = (const float*)d_in[11];
    const float* prm_b   = (const float*)d_in[12];
    const float* pred_w1 = (const float*)d_in[13];
    const float* pred_b1 = (const float*)d_in[14];
    const float* pred_w2 = (const float*)d_in[15];
    const float* pred_b2 = (const float*)d_in[16];
    const float* q_w     = (const float*)d_in[17];
    const float* q_b     = (const float*)d_in[18];
    const float* k_w     = (const float*)d_in[19];
    const float* k_b     = (const float*)d_in[20];
    float* out = (float*)d_out;

    cudaFuncSetAttribute(k_sig_mma, cudaFuncAttributeMaxDynamicSharedMemorySize, SM2_TOTAL);

    k_wsplit<<<1024, 256>>>(sig_w);
    k_pool<<<dim3(B_IMG, 9), 128>>>(ov, pool_w);
    k_cls1<<<64, 256>>>(cls_w1, cls_b1, pool_b);
    k_cls2<<<64, 256>>>(cls_w2, cls_b2);
    k_puv<<<dim3(16, NL), 256>>>(emo, prm_w);
    k_prompts2<<<dim3(NE, B_IMG, NL), 256>>>(prm_b);
    k_sig_mma<<<dim3(12, T_TOK, NL * 2), 256, SM2_TOTAL>>>(sig, sig_b);
    k_softmax_mean<<<T_TOK * NE, 256>>>();
    k_matt<<<T_TOK, 256>>>();
    k_tok<<<dim3(T_TOK, 9), 128>>>(ov);
    k_qproj<<<T_TOK, 256>>>(q_w, q_b);
    k_kq<<<dim3(T_TOK, 9), 256>>>(k_w, k_b);
    k_logits<<<dim3(T_TOK, 6), 128>>>(ov);
    k_soft4<<<T_TOK, 256>>>();
    k_major<<<dim3(T_TOK, 9), 128>>>(ov, out);
    k_finpred<<<B_IMG, 256>>>(pred_w1, pred_b1, pred_w2, pred_b2, out);
}

// round 17
// speedup vs baseline: 1.0472x; 1.0472x over previous
#include <cuda_runtime.h>
#include <cuda_fp16.h>
#include <math.h>
#include <stdint.h>

#define T_TOK 64
#define S_SP  729
#define H_DIM 1152
#define E_DIM 512
#define NE    9
#define NL    4
#define B_IMG 8
#define P_PAT 8

#define OUT_MAJOR 0
#define OUT_FINAL (T_TOK * 4 * H_DIM)
#define OUT_PREDS (OUT_FINAL + B_IMG * H_DIM)

__device__ float g_poolpart[B_IMG * 9 * H_DIM];
__device__ float g_hidden [B_IMG * E_DIM];
__device__ float g_cls    [B_IMG * E_DIM];
__device__ float g_puv    [NL * 17 * E_DIM];
__device__ float g_prompts[NL * B_IMG * NE * E_DIM];
__device__ float g_part   [(size_t)NL * T_TOK * 2 * 10 * S_SP];
__device__ float g_meanatt[T_TOK * NE * S_SP];
__device__ float g_pes    [T_TOK * NE];
__device__ float g_gsig   [T_TOK * 4];
__device__ float g_tokens [T_TOK * 4 * H_DIM];
__device__ float g_Q      [T_TOK * 4 * E_DIM];
__device__ float g_KQ     [T_TOK * 4 * H_DIM];
__device__ float g_qkb    [T_TOK * 4];
__device__ float g_law    [T_TOK * 4 * 736];
__device__ __align__(16) __half g_Whi[(size_t)NL * E_DIM * H_DIM];

#define WSCALE 32.0f

__device__ __forceinline__ uint32_t smem_u32(const void* p) {
    uint32_t a;
    asm("{ .reg .u64 t; cvta.to.shared.u64 t, %1; cvt.u32.u64 %0, t; }" : "=r"(a) : "l"(p));
    return a;
}
__device__ __forceinline__ void cpasync16(uint32_t dst, const void* src) {
    asm volatile("cp.async.cg.shared.global [%0], [%1], 16;" :: "r"(dst), "l"(src));
}
#define CP_COMMIT() asm volatile("cp.async.commit_group;" ::: "memory")
#define CP_WAIT1()  asm volatile("cp.async.wait_group 1;" ::: "memory")

__device__ __forceinline__ float blockSum256(float v) {
    __shared__ float red[8];
    int lane = threadIdx.x & 31, wid = threadIdx.x >> 5;
    #pragma unroll
    for (int o = 16; o; o >>= 1) v += __shfl_xor_sync(0xffffffffu, v, o);
    if (lane == 0) red[wid] = v;
    __syncthreads();
    if (wid == 0) {
        float r = (lane < 8) ? red[lane] : 0.f;
        #pragma unroll
        for (int o = 4; o; o >>= 1) r += __shfl_xor_sync(0xffffffffu, r, o);
        if (lane == 0) red[0] = r;
    }
    __syncthreads();
    float r = red[0];
    __syncthreads();
    return r;
}
__device__ __forceinline__ float blockMax256(float v) {
    __shared__ float red[8];
    int lane = threadIdx.x & 31, wid = threadIdx.x >> 5;
    #pragma unroll
    for (int o = 16; o; o >>= 1) v = fmaxf(v, __shfl_xor_sync(0xffffffffu, v, o));
    if (lane == 0) red[wid] = v;
    __syncthreads();
    if (wid == 0) {
        float r = (lane < 8) ? red[lane] : -INFINITY;
        #pragma unroll
        for (int o = 4; o; o >>= 1) r = fmaxf(r, __shfl_xor_sync(0xffffffffu, r, o));
        if (lane == 0) red[0] = r;
    }
    __syncthreads();
    float r = red[0];
    __syncthreads();
    return r;
}
__device__ __forceinline__ float blockSum128(float v) {
    __shared__ float red[4];
    int lane = threadIdx.x & 31, wid = threadIdx.x >> 5;
    #pragma unroll
    for (int o = 16; o; o >>= 1) v += __shfl_xor_sync(0xffffffffu, v, o);
    if (lane == 0) red[wid] = v;
    __syncthreads();
    if (wid == 0) {
        float r = (lane < 4) ? red[lane] : 0.f;
        #pragma unroll
        for (int o = 2; o; o >>= 1) r += __shfl_xor_sync(0xffffffffu, r, o);
        if (lane == 0) red[0] = r;
    }
    __syncthreads();
    float r = red[0];
    __syncthreads();
    return r;
}
__device__ __forceinline__ float blockMax128(float v) {
    __shared__ float red[4];
    int lane = threadIdx.x & 31, wid = threadIdx.x >> 5;
    #pragma unroll
    for (int o = 16; o; o >>= 1) v = fmaxf(v, __shfl_xor_sync(0xffffffffu, v, o));
    if (lane == 0) red[wid] = v;
    __syncthreads();
    if (wid == 0) {
        float r = (lane < 4) ? red[lane] : -INFINITY;
        #pragma unroll
        for (int o = 2; o; o >>= 1) r = fmaxf(r, __shfl_xor_sync(0xffffffffu, r, o));
        if (lane == 0) red[0] = r;
    }
    __syncthreads();
    float r = red[0];
    __syncthreads();
    return r;
}
__device__ __forceinline__ float gelu_exact(float x) {
    return 0.5f * x * (1.0f + erff(x * 0.7071067811865475f));
}
__device__ __forceinline__ uint32_t pk2h(__half a, __half b) {
    return ((uint32_t)__half_as_ushort(b) << 16) | (uint32_t)__half_as_ushort(a);
}
__device__ __forceinline__ void mmaf16(float* d, const uint32_t* a, uint32_t b0, uint32_t b1) {
    asm volatile(
        "mma.sync.aligned.m16n8k16.row.col.f32.f16.f16.f32 "
        "{%0,%1,%2,%3}, {%4,%5,%6,%7}, {%8,%9}, {%0,%1,%2,%3};"
        : "+f"(d[0]), "+f"(d[1]), "+f"(d[2]), "+f"(d[3])
        : "r"(a[0]), "r"(a[1]), "r"(a[2]), "r"(a[3]), "r"(b0), "r"(b1));
}

__global__ void k_wsplit(const float* __restrict__ sw) {
    const size_t N = (size_t)NL * E_DIM * H_DIM;
    for (size_t i = (size_t)blockIdx.x * 256 + threadIdx.x; i < N; i += (size_t)gridDim.x * 256)
        g_Whi[i] = __float2half(sw[i] * WSCALE);
}

__global__ void k_pool(const float* __restrict__ ov, const float* __restrict__ pw) {
    int b = blockIdx.x, sc = blockIdx.y, tid = threadIdx.x;
    float acc[9];
    #pragma unroll
    for (int j = 0; j < 9; j++) acc[j] = 0.f;
    const float* base = ov + (size_t)(b * P_PAT) * S_SP * H_DIM + (size_t)sc * 81 * H_DIM + tid;
    for (int s = 0; s < 81; s++) {
        float w = pw[sc * 81 + s];
        const float* p = base + (size_t)s * H_DIM;
        #pragma unroll
        for (int j = 0; j < 9; j++) acc[j] += w * p[j * 128];
    }
    #pragma unroll
    for (int j = 0; j < 9; j++)
        g_poolpart[((size_t)b * 9 + sc) * H_DIM + tid + j * 128] = acc[j];
}

__global__ void k_cls1(const float* __restrict__ w1, const float* __restrict__ b1,
                       const float* __restrict__ pb) {
    __shared__ float pr[B_IMG * H_DIM];
    int tid = threadIdx.x, wid = tid >> 5, lane = tid & 31;
    float pbias = pb[0];
    for (int idx = tid; idx < B_IMG * H_DIM; idx += 256) {
        int b = idx / H_DIM, h = idx - b * H_DIM;
        float s = pbias;
        #pragma unroll
        for (int sc = 0; sc < 9; sc++) s += g_poolpart[((size_t)b * 9 + sc) * H_DIM + h];
        pr[idx] = s;
    }
    __syncthreads();
    int o = blockIdx.x * 8 + wid;
    float acc[8];
    #pragma unroll
    for (int b = 0; b < 8; b++) acc[b] = 0.f;
    const float* wr = w1 + (size_t)o * H_DIM;
    for (int k = lane; k < H_DIM; k += 32) {
        float w = wr[k];
        #pragma unroll
        for (int b = 0; b < 8; b++) acc[b] += w * pr[b * H_DIM + k];
    }
    #pragma unroll
    for (int b = 0; b < 8; b++)
        #pragma unroll
        for (int off = 16; off; off >>= 1) acc[b] += __shfl_xor_sync(0xffffffffu, acc[b], off);
    if (lane == 0) {
        float bv = b1[o];
        #pragma unroll
        for (int b = 0; b < 8; b++) g_hidden[b * E_DIM + o] = gelu_exact(acc[b] + bv);
    }
}

__global__ void k_cls2(const float* __restrict__ w2, const float* __restrict__ b2) {
    __shared__ float hr[B_IMG * E_DIM];
    int tid = threadIdx.x, wid = tid >> 5, lane = tid & 31;
    for (int idx = tid; idx < B_IMG * E_DIM; idx += 256) hr[idx] = g_hidden[idx];
    __syncthreads();
    int o = blockIdx.x * 8 + wid;
    float acc[8];
    #pragma unroll
    for (int b = 0; b < 8; b++) acc[b] = 0.f;
    const float* wr = w2 + (size_t)o * E_DIM;
    for (int k = lane; k < E_DIM; k += 32) {
        float w = wr[k];
        #pragma unroll
        for (int b = 0; b < 8; b++) acc[b] += w * hr[b * E_DIM + k];
    }
    #pragma unroll
    for (int b = 0; b < 8; b++)
        #pragma unroll
        for (int off = 16; off; off >>= 1) acc[b] += __shfl_xor_sync(0xffffffffu, acc[b], off);
    if (lane == 0) {
        float bv = b2[o];
        #pragma unroll
        for (int b = 0; b < 8; b++) g_cls[b * E_DIM + o] = acc[b] + bv;
    }
}

__global__ void k_puv(const float* __restrict__ emo, const float* __restrict__ pw) {
    int oc = blockIdx.x, i = blockIdx.y;
    int tid = threadIdx.x, wid = tid >> 5, lane = tid & 31;
    __shared__ float es[NE * E_DIM];
    __shared__ float cs[B_IMG * E_DIM];
    for (int idx = tid; idx < NE * E_DIM; idx += 256) es[idx] = emo[idx];
    for (int idx = tid; idx < B_IMG * E_DIM; idx += 256) cs[idx] = g_cls[idx];
    __syncthreads();
    for (int oi = wid; oi < 32; oi += 8) {
        int o = oc * 32 + oi;
        const float* wr = pw + ((size_t)i * E_DIM + o) * 1024;
        float acc[17];
        #pragma unroll
        for (int j = 0; j < 17; j++) acc[j] = 0.f;
        for (int c = lane; c < 512; c += 32) {
            float w1 = wr[c];
            #pragma unroll
            for (int n = 0; n < NE; n++) acc[n] += w1 * es[n * 512 + c];
            float w2 = wr[512 + c];
            #pragma unroll
            for (int b = 0; b < B_IMG; b++) acc[9 + b] += w2 * cs[b * 512 + c];
        }
        #pragma unroll
        for (int j = 0; j < 17; j++)
            #pragma unroll
            for (int off = 16; off; off >>= 1) acc[j] += __shfl_xor_sync(0xffffffffu, acc[j], off);
        if (lane == 0) {
            #pragma unroll
            for (int j = 0; j < 17; j++) g_puv[((size_t)i * 17 + j) * 512 + o] = acc[j];
        }
    }
}

__global__ void k_prompts2(const float* __restrict__ pb) {
    int n = blockIdx.x, b = blockIdx.y, i = blockIdx.z;
    int tid = threadIdx.x;
    int o1 = tid, o2 = tid + 256;
    float r1 = g_puv[((size_t)i * 17 + n) * 512 + o1] + g_puv[((size_t)i * 17 + 9 + b) * 512 + o1]
             + pb[i * 512 + o1];
    float r2 = g_puv[((size_t)i * 17 + n) * 512 + o2] + g_puv[((size_t)i * 17 + 9 + b) * 512 + o2]
             + pb[i * 512 + o2];
    float nrm = blockSum256(r1 * r1 + r2 * r2);
    float inv = rsqrtf(nrm);
    size_t base = ((size_t)(i * B_IMG + b) * NE + n) * E_DIM;
    g_prompts[base + o1] = r1 * inv;
    g_prompts[base + o2] = r2 * inv;
}

// ======= sig GEMM (R15 winner, byte-identical): fp16 single product, 2 CTA/SM =======
#define NCH 36
#define SM2_PSM   0
#define SM2_SBI   9216
#define SM2_RED   10240
#define SM2_A     12800
#define SM2_W     23040
#define SM2_YSM   12800
#define SM2_TOTAL 79360
#define Y_STR 260

__global__ void __launch_bounds__(256, 2)
k_sig_mma(const float* __restrict__ sig, const float* __restrict__ sb) {
    extern __shared__ char smem[];
    uint32_t sbase = smem_u32(smem);
    float* Psm = reinterpret_cast<float*>(smem + SM2_PSM);
    float* Sbi = reinterpret_cast<float*>(smem + SM2_SBI);
    float* red = reinterpret_cast<float*>(smem + SM2_RED);
    float* ysm = reinterpret_cast<float*>(smem + SM2_YSM);

    int tid = threadIdx.x, wid = tid >> 5, lane = tid & 31;
    int wm = wid >> 2, wn = wid & 3;
    int g = lane >> 2, tig = lane & 3;
    int s0 = blockIdx.x * 64;
    int t = blockIdx.y;
    int i = blockIdx.z >> 1, half = blockIdx.z & 1;
    int b = t >> 3;

    {
        size_t pbase = ((size_t)(i * B_IMG + b) * NE) * E_DIM + half * 256;
        for (int idx = tid; idx < NE * 256; idx += 256) {
            int n = idx >> 8, cc = idx & 255;
            Psm[idx] = g_prompts[pbase + (size_t)n * E_DIM + cc];
        }
        for (int idx = tid; idx < 256; idx += 256)
            Sbi[idx] = WSCALE * sb[i * E_DIM + half * 256 + idx];
        for (int idx = tid; idx < 640; idx += 256) red[idx] = 0.f;
    }

    const float* Xbase = sig + ((size_t)(i * T_TOK + t) * S_SP) * H_DIM;
    const char* WH = reinterpret_cast<const char*>(g_Whi)
                   + ((size_t)i * E_DIM + half * 256) * H_DIM * 2;

    float acc[2][8][4];
    #pragma unroll
    for (int mt = 0; mt < 2; mt++)
        #pragma unroll
        for (int nt = 0; nt < 8; nt++)
            #pragma unroll
            for (int c = 0; c < 4; c++) acc[mt][nt][c] = 0.f;

    int xrow = tid >> 2, xkc = tid & 3;
    int xs = s0 + xrow;
    const float* xptr = (xs < S_SP) ? (Xbase + (size_t)xs * H_DIM + xkc * 8) : nullptr;
    float xv[8];

#define ISSUE_W(CH, BUF) do { \
    const char* sH = WH + ((size_t)tid * H_DIM + (CH) * 32) * 2; \
    uint32_t dH = sbase + SM2_W + (BUF) * 20480 + tid * 80; \
    cpasync16(dH, sH); cpasync16(dH + 16, sH + 16); \
    cpasync16(dH + 32, sH + 32); cpasync16(dH + 48, sH + 48); \
} while (0)

#define LOAD_X(CH) do { \
    if (xptr) { \
        const float* p_ = xptr + (CH) * 32; \
        float4 f0_ = *reinterpret_cast<const float4*>(p_); \
        float4 f1_ = *reinterpret_cast<const float4*>(p_ + 4); \
        xv[0]=f0_.x; xv[1]=f0_.y; xv[2]=f0_.z; xv[3]=f0_.w; \
        xv[4]=f1_.x; xv[5]=f1_.y; xv[6]=f1_.z; xv[7]=f1_.w; \
    } else { \
        _Pragma("unroll") for (int j_ = 0; j_ < 8; j_++) xv[j_] = 0.f; \
    } \
} while (0)

#define STORE_A(BUF) do { \
    uint32_t hq_[4]; \
    _Pragma("unroll") \
    for (int j_ = 0; j_ < 4; j_++) \
        hq_[j_] = pk2h(__float2half(xv[2*j_]), __float2half(xv[2*j_+1])); \
    char* aH = smem + SM2_A + (BUF) * 5120 + xrow * 80 + xkc * 16; \
    *reinterpret_cast<uint4*>(aH) = make_uint4(hq_[0], hq_[1], hq_[2], hq_[3]); \
} while (0)

    ISSUE_W(0, 0); CP_COMMIT();
    LOAD_X(0);
    ISSUE_W(1, 1); CP_COMMIT();
    STORE_A(0);
    LOAD_X(1);

    for (int ch = 0; ch < NCH; ch++) {
        int buf = ch & 1;
        if (ch > 0) {
            STORE_A(buf);
            if (ch + 1 < NCH) LOAD_X(ch + 1);
        }
        CP_WAIT1();
        __syncthreads();

        const uint32_t* AH  = reinterpret_cast<const uint32_t*>(smem + SM2_A + buf * 5120);
        const uint32_t* WHs = reinterpret_cast<const uint32_t*>(smem + SM2_W + buf * 20480);

        #pragma unroll
        for (int h = 0; h < 2; h++) {
            uint32_t ah[2][4];
            #pragma unroll
            for (int mt = 0; mt < 2; mt++) {
                int base = (wm * 32 + mt * 16 + g) * 20 + h * 8 + tig;
                ah[mt][0] = AH[base];     ah[mt][1] = AH[base + 160];
                ah[mt][2] = AH[base + 4]; ah[mt][3] = AH[base + 164];
            }
            #pragma unroll
            for (int nt = 0; nt < 8; nt++) {
                int wb = (wn * 64 + nt * 8 + g) * 20 + h * 8 + tig;
                uint32_t b0h = WHs[wb], b1h = WHs[wb + 4];
                mmaf16(acc[0][nt], ah[0], b0h, b1h);
                mmaf16(acc[1][nt], ah[1], b0h, b1h);
            }
        }
        __syncthreads();
        if (ch + 2 < NCH) ISSUE_W(ch + 2, buf);
        CP_COMMIT();
    }

    #pragma unroll
    for (int mt = 0; mt < 2; mt++) {
        int row = wm * 32 + mt * 16 + g;
        #pragma unroll
        for (int nt = 0; nt < 8; nt++) {
            int col = wn * 64 + nt * 8 + tig * 2;
            float b0 = Sbi[col], b1 = Sbi[col + 1];
            *reinterpret_cast<float2*>(&ysm[row * Y_STR + col]) =
                make_float2(acc[mt][nt][0] + b0, acc[mt][nt][1] + b1);
            *reinterpret_cast<float2*>(&ysm[(row + 8) * Y_STR + col]) =
                make_float2(acc[mt][nt][2] + b0, acc[mt][nt][3] + b1);
        }
    }
    __syncthreads();
    for (int r8 = 0; r8 < 8; r8++) {
        int row = wid * 8 + r8;
        float v[10];
        #pragma unroll
        for (int j = 0; j < 10; j++) v[j] = 0.f;
        for (int cc = lane; cc < 256; cc += 32) {
            float y = ysm[row * Y_STR + cc];
            v[0] += y * y;
            #pragma unroll
            for (int n = 0; n < NE; n++) v[1 + n] += y * Psm[n * 256 + cc];
        }
        #pragma unroll
        for (int j = 0; j < 10; j++)
            #pragma unroll
            for (int off = 16; off; off >>= 1) v[j] += __shfl_xor_sync(0xffffffffu, v[j], off);
        if (lane == 0) {
            #pragma unroll
            for (int j = 0; j < 10; j++) red[row * 10 + j] = v[j];
        }
    }
    __syncthreads();

    if (tid < 64) {
        int s = s0 + tid;
        if (s < S_SP) {
            size_t base = ((((size_t)i * T_TOK + t) * 2 + half) * 10) * S_SP + s;
            #pragma unroll
            for (int j = 0; j < 10; j++)
                g_part[base + (size_t)j * S_SP] = red[tid * 10 + j];
        }
    }
#undef ISSUE_W
#undef LOAD_X
#undef STORE_A
}

__global__ void k_softmax_mean() {
    int tn = blockIdx.x;
    int t = tn / NE, n = tn % NE;
    int tid = threadIdx.x;
    float accm[3] = {0.f, 0.f, 0.f};
    for (int i = 0; i < NL; i++) {
        const float* p0 = g_part + ((((size_t)i * T_TOK + t) * 2 + 0) * 10) * S_SP;
        const float* p1 = g_part + ((((size_t)i * T_TOK + t) * 2 + 1) * 10) * S_SP;
        float x[3];
        float mx = -INFINITY;
        #pragma unroll
        for (int j = 0; j < 3; j++) {
            int s = tid + j * 256;
            if (s < S_SP) {
                float nsq = p0[s] + p1[s];
                float d = p0[(size_t)(1 + n) * S_SP + s] + p1[(size_t)(1 + n) * S_SP + s];
                x[j] = 100.f * d * rsqrtf(nsq);
            } else x[j] = -INFINITY;
            mx = fmaxf(mx, x[j]);
        }
        mx = blockMax256(mx);
        float lsum = 0.f;
        float e[3];
        #pragma unroll
        for (int j = 0; j < 3; j++) {
            int s = tid + j * 256;
            e[j] = (s < S_SP) ? expf(x[j] - mx) : 0.f;
            lsum += e[j];
        }
        float tot = blockSum256(lsum);
        float inv = 0.25f / tot;
        #pragma unroll
        for (int j = 0; j < 3; j++) accm[j] += e[j] * inv;
    }
    float psum = 0.f;
    size_t obase = ((size_t)t * NE + n) * S_SP;
    #pragma unroll
    for (int j = 0; j < 3; j++) {
        int s = tid + j * 256;
        if (s < S_SP) {
            g_meanatt[obase + s] = accm[j];
            psum += accm[j];
        }
    }
    float tot = blockSum256(psum);
    if (tid == 0) g_pes[t * NE + n] = tot / (float)S_SP;
}

// tokens with fused quadrant-weight computation: grid (64, 9), block 128
__global__ void k_tok(const float* __restrict__ ov) {
    __shared__ float wqs[4 * 736];
    int t = blockIdx.x, hc = blockIdx.y, tid = threadIdx.x;

    float bsum[4] = {0.f, 0.f, 0.f, 0.f};
    for (int s = tid; s < 736; s += 128) {
        float w0 = 0.f, w1 = 0.f, w2 = 0.f, w3 = 0.f;
        if (s < S_SP) {
            float m = -INFINITY;
            #pragma unroll
            for (int n = 0; n < NE; n++)
                m = fmaxf(m, g_meanatt[((size_t)t * NE + n) * S_SP + s]);
            int r = s / 27, c = s - r * 27;
            w0 = (r < 14 && c < 14) ? m : 0.f;
            w1 = (r < 14 && c >= 13) ? m : 0.f;
            w2 = (r >= 13 && c < 14) ? m : 0.f;
            w3 = (r >= 13 && c >= 13) ? m : 0.f;
        }
        wqs[s] = w0;
        wqs[736 + s] = w1;
        wqs[1472 + s] = w2;
        wqs[2208 + s] = w3;
        bsum[0] += w0; bsum[1] += w1; bsum[2] += w2; bsum[3] += w3;
    }
    float spv[4];
    #pragma unroll
    for (int q = 0; q < 4; q++) spv[q] = blockSum128(bsum[q]) / 196.f;
    if (hc == 0 && tid == 0) {
        float pm = -INFINITY;
        for (int n = 0; n < NE; n++) pm = fmaxf(pm, g_pes[t * NE + n]);
        g_gsig[t * 4 + 0] = spv[0] * pm;
        g_gsig[t * 4 + 1] = spv[1] * pm;
        g_gsig[t * 4 + 2] = spv[2] * pm;
        g_gsig[t * 4 + 3] = spv[3] * pm;
    }
    __syncthreads();

    int h = hc * 128 + tid;
    float a0 = 0.f, a1 = 0.f, a2 = 0.f, a3 = 0.f;
    const float* base = ov + ((size_t)t * S_SP) * H_DIM + h;
    for (int s = 0; s < S_SP; s++) {
        float v = base[(size_t)s * H_DIM];
        a0 += v * wqs[s];
        a1 += v * wqs[736 + s];
        a2 += v * wqs[1472 + s];
        a3 += v * wqs[2208 + s];
    }
    g_tokens[((size_t)t * 4 + 0) * H_DIM + h] = (a0 * (1.f / 196.f)) / (spv[0] + 1e-8f);
    g_tokens[((size_t)t * 4 + 1) * H_DIM + h] = (a1 * (1.f / 196.f)) / (spv[1] + 1e-8f);
    g_tokens[((size_t)t * 4 + 2) * H_DIM + h] = (a2 * (1.f / 196.f)) / (spv[2] + 1e-8f);
    g_tokens[((size_t)t * 4 + 3) * H_DIM + h] = (a3 * (1.f / 196.f)) / (spv[3] + 1e-8f);
}

__global__ void k_qproj(const float* __restrict__ qw, const float* __restrict__ qb) {
    int t = blockIdx.x, tid = threadIdx.x;
    __shared__ float toks[4 * H_DIM];
    for (int idx = tid; idx < 4 * H_DIM; idx += 256) toks[idx] = g_tokens[(size_t)t * 4 * H_DIM + idx];
    __syncthreads();
    int wid = tid >> 5, lane = tid & 31;
    for (int o = wid; o < E_DIM; o += 8) {
        float acc[4] = {0.f, 0.f, 0.f, 0.f};
        const float* wr = qw + (size_t)o * H_DIM;
        for (int k = lane; k < H_DIM; k += 32) {
            float w = wr[k];
            #pragma unroll
            for (int q = 0; q < 4; q++) acc[q] += w * toks[q * H_DIM + k];
        }
        #pragma unroll
        for (int off = 16; off; off >>= 1)
            #pragma unroll
            for (int q = 0; q < 4; q++) acc[q] += __shfl_xor_sync(0xffffffffu, acc[q], off);
        if (lane == 0) {
            float bv = qb[o];
            #pragma unroll
            for (int q = 0; q < 4; q++) g_Q[((size_t)t * 4 + q) * E_DIM + o] = acc[q] + bv;
        }
    }
}

__global__ void k_kq(const float* __restrict__ kw, const float* __restrict__ kb) {
    int t = blockIdx.x, hc = blockIdx.y;
    int tid = threadIdx.x;
    __shared__ float Qs[4 * E_DIM];
    for (int idx = tid; idx < 4 * E_DIM; idx += 256) Qs[idx] = g_Q[(size_t)t * 4 * E_DIM + idx];
    __syncthreads();
    int h = hc * 128 + (tid >> 1);
    int q0 = (tid & 1) * 2;
    float a0 = 0.f, a1 = 0.f;
    const float* kcol = kw + h;
    for (int e = 0; e < E_DIM; e++) {
        float kv = kcol[(size_t)e * H_DIM];
        a0 += kv * Qs[(q0 + 0) * E_DIM + e];
        a1 += kv * Qs[(q0 + 1) * E_DIM + e];
    }
    g_KQ[((size_t)t * 4 + q0 + 0) * H_DIM + h] = a0;
    g_KQ[((size_t)t * 4 + q0 + 1) * H_DIM + h] = a1;

    if (hc == 0 && tid < 128) {
        int wid = tid >> 5, lane = tid & 31;
        float acc = 0.f;
        for (int e = lane; e < E_DIM; e += 32) acc += Qs[wid * E_DIM + e] * kb[e];
        #pragma unroll
        for (int off = 16; off; off >>= 1) acc += __shfl_xor_sync(0xffffffffu, acc, off);
        if (lane == 0) g_qkb[t * 4 + wid] = acc;
    }
}

__global__ void k_logits(const float* __restrict__ ov) {
    __shared__ float KQs[4 * H_DIM];
    __shared__ float qkbs[4];
    int t = blockIdx.x, sc = blockIdx.y, tid = threadIdx.x;
    int wid = tid >> 5, lane = tid & 31;
    for (int idx = tid; idx < 4 * H_DIM; idx += 128) KQs[idx] = g_KQ[(size_t)t * 4 * H_DIM + idx];
    if (tid < 4) qkbs[tid] = g_qkb[t * 4 + tid];
    __syncthreads();
    const float RS = 0.04419417382415922f;
    for (int s = sc * 128 + wid; s < min(sc * 128 + 128, S_SP); s += 4) {
        float acc[4] = {0.f, 0.f, 0.f, 0.f};
        const float* orow = ov + ((size_t)t * S_SP + s) * H_DIM;
        for (int h = lane; h < H_DIM; h += 32) {
            float vv = orow[h];
            #pragma unroll
            for (int q = 0; q < 4; q++) acc[q] += vv * KQs[q * H_DIM + h];
        }
        #pragma unroll
        for (int off = 16; off; off >>= 1)
            #pragma unroll
            for (int q = 0; q < 4; q++) acc[q] += __shfl_xor_sync(0xffffffffu, acc[q], off);
        if (lane == 0) {
            #pragma unroll
            for (int q = 0; q < 4; q++)
                g_law[((size_t)t * 4 + q) * 736 + s] = (acc[q] + qkbs[q]) * RS;
        }
    }
}

// major with fused 4-way softmax: grid (64, 9), block 128
__global__ void k_major(const float* __restrict__ ov, float* __restrict__ out) {
    __shared__ float law[4 * 736];
    int t = blockIdx.x, hc = blockIdx.y, tid = threadIdx.x;
    for (int idx = tid; idx < 4 * 736; idx += 128) {
        int q = idx / 736, s = idx - q * 736;
        law[idx] = (s < S_SP) ? g_law[((size_t)t * 4 + q) * 736 + s] : 0.f;
    }
    __syncthreads();

    // per-q softmax (redundant across hc blocks; deterministic)
    #pragma unroll
    for (int q = 0; q < 4; q++) {
        float mx = -INFINITY;
        #pragma unroll
        for (int j = 0; j < 6; j++) {
            int s = tid + j * 128;
            if (s < S_SP) mx = fmaxf(mx, law[q * 736 + s]);
        }
        mx = blockMax128(mx);
        float lsum = 0.f;
        float e[6];
        #pragma unroll
        for (int j = 0; j < 6; j++) {
            int s = tid + j * 128;
            e[j] = (s < S_SP) ? expf(law[q * 736 + s] - mx) : 0.f;
            lsum += e[j];
        }
        float tot = blockSum128(lsum);
        float inv = 1.f / tot;
        #pragma unroll
        for (int j = 0; j < 6; j++) {
            int s = tid + j * 128;
            if (s < 736) law[q * 736 + s] = e[j] * inv;
        }
        __syncthreads();
    }

    int h = hc * 128 + tid;
    float a0 = 0.f, a1 = 0.f, a2 = 0.f, a3 = 0.f;
    const float* base = ov + ((size_t)t * S_SP) * H_DIM + h;
    for (int s = 0; s < S_SP; s++) {
        float v = base[(size_t)s * H_DIM];
        a0 += v * law[s];
        a1 += v * law[736 + s];
        a2 += v * law[1472 + s];
        a3 += v * law[2208 + s];
    }
    out[OUT_MAJOR + ((size_t)t * 4 + 0) * H_DIM + h] = a0;
    out[OUT_MAJOR + ((size_t)t * 4 + 1) * H_DIM + h] = a1;
    out[OUT_MAJOR + ((size_t)t * 4 + 2) * H_DIM + h] = a2;
    out[OUT_MAJOR + ((size_t)t * 4 + 3) * H_DIM + h] = a3;
}

__global__ void k_finpred(const float* __restrict__ w1, const float* __restrict__ b1,
                          const float* __restrict__ w2, const float* __restrict__ b2,
                          float* __restrict__ out) {
    int b = blockIdx.x, tid = threadIdx.x;
    __shared__ float gsh[32];
    __shared__ float gsum_sh;
    __shared__ float fr[H_DIM];
    __shared__ float hid[E_DIM];
    __shared__ float lg[NE];
    if (tid < 32) {
        int p = tid >> 2, q = tid & 3;
        gsh[tid] = g_gsig[(b * P_PAT + p) * 4 + q];
    }
    __syncthreads();
    if (tid == 0) {
        float s = 0.f;
        for (int i = 0; i < 32; i++) s += gsh[i];
        gsum_sh = s;
    }
    __syncthreads();
    float denom = gsum_sh / 32.f + 1e-8f;
    int nh = (tid < 128) ? 5 : 4;
    for (int j = 0; j < nh; j++) {
        int h = tid + j * 256;
        float acc = 0.f;
        for (int idx = 0; idx < 32; idx++) {
            int p = idx >> 2, q = idx & 3;
            acc += out[OUT_MAJOR + ((size_t)(b * P_PAT + p) * 4 + q) * H_DIM + h] * gsh[idx];
        }
        float fin = (acc / 32.f) / denom;
        fr[h] = fin;
        out[OUT_FINAL + (size_t)b * H_DIM + h] = fin;
    }
    __syncthreads();
    int wid = tid >> 5, lane = tid & 31;
    for (int o = wid; o < E_DIM; o += 8) {
        float acc = 0.f;
        const float* wr = w1 + (size_t)o * H_DIM;
        for (int k = lane; k < H_DIM; k += 32) acc += wr[k] * fr[k];
        #pragma unroll
        for (int off = 16; off; off >>= 1) acc += __shfl_xor_sync(0xffffffffu, acc, off);
        if (lane == 0) hid[o] = gelu_exact(acc + b1[o]);
    }
    __syncthreads();
    for (int n = 0; n < NE; n++) {
        float v = hid[tid] * w2[n * E_DIM + tid] + hid[tid + 256] * w2[n * E_DIM + tid + 256];
        float tot = blockSum256(v);
        if (tid == 0) lg[n] = tot + b2[n];
    }
    __syncthreads();
    if (tid == 0) {
        float mx = -INFINITY;
        for (int n = 0; n < NE; n++) mx = fmaxf(mx, lg[n]);
        float sum = 0.f;
        float e[NE];
        for (int n = 0; n < NE; n++) { e[n] = expf(lg[n] - mx); sum += e[n]; }
        for (int n = 0; n < NE; n++) out[OUT_PREDS + b * NE + n] = e[n] / sum;
    }
}

extern "C" void kernel_launch(void* const* d_in, const int* in_sizes, int n_in,
                              void* d_out, int out_size) {
    const float* ov      = (const float*)d_in[0];
    const float* sig     = (const float*)d_in[1];
    const float* emo     = (const float*)d_in[2];
    const float* pool_w  = (const float*)d_in[3];
    const float* pool_b  = (const float*)d_in[4];
    const float* cls_w1  = (const float*)d_in[5];
    const float* cls_b1  = (const float*)d_in[6];
    const float* cls_w2  = (const float*)d_in[7];
    const float* cls_b2  = (const float*)d_in[8];
    const float* sig_w   = (const float*)d_in[9];
    const float* sig_b   = (const float*)d_in[10];
    const float* prm_w   = (const float*)d_in[11];
    const float* prm_b   = (const float*)d_in[12];
    const float* pred_w1 = (const float*)d_in[13];
    const float* pred_b1 = (const float*)d_in[14];
    const float* pred_w2 = (const float*)d_in[15];
    const float* pred_b2 = (const float*)d_in[16];
    const float* q_w     = (const float*)d_in[17];
    const float* q_b     = (const float*)d_in[18];
    const float* k_w     = (const float*)d_in[19];
    const float* k_b     = (const float*)d_in[20];
    float* out = (float*)d_out;

    cudaFuncSetAttribute(k_sig_mma, cudaFuncAttributeMaxDynamicSharedMemorySize, SM2_TOTAL);

    k_wsplit<<<1024, 256>>>(sig_w);
    k_pool<<<dim3(B_IMG, 9), 128>>>(ov, pool_w);
    k_cls1<<<64, 256>>>(cls_w1, cls_b1, pool_b);
    k_cls2<<<64, 256>>>(cls_w2, cls_b2);
    k_puv<<<dim3(16, NL), 256>>>(emo, prm_w);
    k_prompts2<<<dim3(NE, B_IMG, NL), 256>>>(prm_b);
    k_sig_mma<<<dim3(12, T_TOK, NL * 2), 256, SM2_TOTAL>>>(sig, sig_b);
    k_softmax_mean<<<T_TOK * NE, 256>>>();
    k_tok<<<dim3(T_TOK, 9), 128>>>(ov);
    k_qproj<<<T_TOK, 256>>>(q_w, q_b);
    k_kq<<<dim3(T_TOK, 9), 256>>>(k_w, k_b);
    k_logits<<<dim3(T_TOK, 6), 128>>>(ov);
    k_major<<<dim3(T_TOK, 9), 128>>>(ov, out);
    k_finpred<<<B_IMG, 256>>>(pred_w1, pred_b1, pred_w2, pred_b2, out);
}